// round 3
// baseline (speedup 1.0000x reference)
#include <cuda_runtime.h>

// ============================================================================
// SRU cell. L=2048, B=16, D=1024.
//   u = x @ W   (32768 x 1024) @ (1024 x 3072)  -> tf32 mma.sync GEMM
//   sequential scan over L on 16384 channels    -> scan kernel
// GEMM inputs pre-rounded to tf32 (RNA) and k-permuted in gmem scratch so the
// mainloop is pure LDS.64 + HMMA.
// ============================================================================

#define L_DIM 2048
#define B_DIM 16
#define D_DIM 1024
#define N_DIM 3072
#define K_DIM 1024
#define M_DIM 32768  // L*B

#define BM 128
#define BN 128
#define BK 16
#define STAGES 4
#define ROWSTR 24                 // floats per smem row (16 + 8 pad): LDS.64 conflict-free
#define KT (K_DIM / BK)           // 64
#define STAGE_F (2 * BM * ROWSTR) // floats per stage (A+B) = 6144
#define GEMM_SMEM_BYTES (STAGES * STAGE_F * 4)  // 98304

// Scratch (allocation-free rule: __device__ globals)
__device__ float g_Xr[(size_t)M_DIM * K_DIM];  // X tf32-rounded + k-permuted (128 MB)
__device__ float g_Wt[N_DIM * K_DIM];          // W^T tf32-rounded + k-permuted (12 MB)
__device__ float g_U[(size_t)M_DIM * N_DIM];   // GEMM output u (402 MB)

// ---------------------------------------------------------------------------
__device__ __forceinline__ unsigned smem_u32(const void* p) {
    unsigned a;
    asm("{ .reg .u64 t; cvta.to.shared.u64 t, %1; cvt.u32.u64 %0, t; }" : "=r"(a) : "l"(p));
    return a;
}

__device__ __forceinline__ unsigned f2tf32(float x) {
    unsigned u;
    asm("cvt.rna.tf32.f32 %0, %1;" : "=r"(u) : "f"(x));
    return u;
}

__device__ __forceinline__ void cp_async16(unsigned dst, const void* src) {
    asm volatile("cp.async.cg.shared.global [%0], [%1], 16;" :: "r"(dst), "l"(src));
}

__device__ __forceinline__ void mma_tf32(float* c, const unsigned* a, const unsigned* b) {
    asm volatile(
        "mma.sync.aligned.m16n8k8.row.col.f32.tf32.tf32.f32 "
        "{%0,%1,%2,%3}, {%4,%5,%6,%7}, {%8,%9}, {%0,%1,%2,%3};"
        : "+f"(c[0]), "+f"(c[1]), "+f"(c[2]), "+f"(c[3])
        : "r"(a[0]), "r"(a[1]), "r"(a[2]), "r"(a[3]), "r"(b[0]), "r"(b[1]));
}

// ---------------------------------------------------------------------------
// Kernel 0: round X to tf32 and k-permute: phys(k) = (k&~7)|((k&3)<<1)|((k>>2)&1)
// Each thread handles one 8-group: phys[0..3]={k0,k4,k1,k5}, phys[4..7]={k2,k6,k3,k7}
// ---------------------------------------------------------------------------
__global__ void __launch_bounds__(256) round_x(const float* __restrict__ X) {
    size_t i8 = (size_t)blockIdx.x * 256 + threadIdx.x;   // group index
    size_t base = i8 * 8;
    float4 i0 = *(const float4*)(X + base);
    float4 i1 = *(const float4*)(X + base + 4);
    uint4 o0, o1;
    o0.x = f2tf32(i0.x); o0.y = f2tf32(i1.x); o0.z = f2tf32(i0.y); o0.w = f2tf32(i1.y);
    o1.x = f2tf32(i0.z); o1.y = f2tf32(i1.z); o1.z = f2tf32(i0.w); o1.w = f2tf32(i1.w);
    *(uint4*)(g_Xr + base) = o0;
    *(uint4*)(g_Xr + base + 4) = o1;
}

// ---------------------------------------------------------------------------
// Kernel 1: transpose + tf32-round + k-permute W (K,N) -> Wt (N,K)
// ---------------------------------------------------------------------------
__global__ void transpose_w(const float* __restrict__ W) {
    __shared__ float t[32][33];
    int n0 = blockIdx.x * 32, k0 = blockIdx.y * 32;
    int tx = threadIdx.x, ty = threadIdx.y;  // 32 x 8
#pragma unroll
    for (int i = 0; i < 32; i += 8)
        t[ty + i][tx] = W[(size_t)(k0 + ty + i) * N_DIM + n0 + tx];
    __syncthreads();
    int ptx = (tx & 24) | ((tx & 3) << 1) | ((tx >> 2) & 1);  // k-permutation
#pragma unroll
    for (int i = 0; i < 32; i += 8) {
        unsigned u = f2tf32(t[tx][ty + i]);
        g_Wt[(size_t)(n0 + ty + i) * K_DIM + k0 + ptx] = __uint_as_float(u);
    }
}

// ---------------------------------------------------------------------------
// Kernel 2: tf32 mma.sync GEMM. CTA 128x128, BK=16, 4-stage cp.async pipeline.
// 8 warps: 4(M) x 2(N); warp tile 32(M) x 64(N); mma m16n8k8.
// All fragment loads are LDS.64 thanks to the gmem k-permutation.
// ---------------------------------------------------------------------------
__global__ void __launch_bounds__(256, 2) gemm_tf32() {
    extern __shared__ float smem_f[];
    unsigned sbase = smem_u32(smem_f);

    int tid = threadIdx.x;
    int wid = tid >> 5;
    int lid = tid & 31;
    int g   = lid >> 2;     // 0..7
    int t4  = lid & 3;      // 0..3
    int warp_m = wid >> 1;  // 0..3
    int warp_n = wid & 1;   // 0..1
    int mbase = warp_m * 32;
    int nbase = warp_n * 64;

    int n0 = blockIdx.x * BN;
    int m0 = blockIdx.y * BM;

    const float* Arow = g_Xr + (size_t)m0 * K_DIM;
    const float* Brow = g_Wt + (size_t)n0 * K_DIM;
    const int B_OFF_F = BM * ROWSTR;

    float acc[2][8][4];
#pragma unroll
    for (int mt = 0; mt < 2; mt++)
#pragma unroll
        for (int nt = 0; nt < 8; nt++)
#pragma unroll
            for (int i = 0; i < 4; i++) acc[mt][nt][i] = 0.0f;

    // stage load: 128 rows x 16 floats (64B = 4 float4) per matrix.
    // 512 chunks per matrix; 256 threads -> 2 A + 2 B chunks each.
    auto load_stage = [&](int stage, int kc) {
        unsigned sA = sbase + (unsigned)(stage * STAGE_F) * 4u;
        unsigned sB = sA + (unsigned)B_OFF_F * 4u;
#pragma unroll
        for (int t = 0; t < 2; t++) {
            int j = tid + t * 256;          // 0..511
            int row = j >> 2;               // 0..127
            int c4 = j & 3;                 // float4 within 16-float row
            unsigned off = (unsigned)(row * ROWSTR + c4 * 4) * 4u;
            cp_async16(sA + off, Arow + (size_t)row * K_DIM + kc + c4 * 4);
            cp_async16(sB + off, Brow + (size_t)row * K_DIM + kc + c4 * 4);
        }
        asm volatile("cp.async.commit_group;" ::: "memory");
    };

#pragma unroll
    for (int s = 0; s < STAGES - 1; s++) load_stage(s, s * BK);

    for (int kt = 0; kt < KT; kt++) {
        asm volatile("cp.async.wait_group %0;" :: "n"(STAGES - 2) : "memory");
        __syncthreads();

        // refill the stage freed by iteration kt-1 (safe: sync above)
        if (kt + STAGES - 1 < KT)
            load_stage((kt + STAGES - 1) % STAGES, (kt + STAGES - 1) * BK);
        else
            asm volatile("cp.async.commit_group;" ::: "memory");

        const float* As = smem_f + (kt % STAGES) * STAGE_F;
        const float* Bs = As + B_OFF_F;

#pragma unroll
        for (int kk = 0; kk < 2; kk++) {
            int kp = kk * 8 + 2 * t4;   // phys offset of (k, k+4) pair
            unsigned a[2][4];
#pragma unroll
            for (int mt = 0; mt < 2; mt++) {
                int m = mbase + mt * 16 + g;
                float2 lo = *(const float2*)(As + m * ROWSTR + kp);
                float2 hi = *(const float2*)(As + (m + 8) * ROWSTR + kp);
                a[mt][0] = __float_as_uint(lo.x);
                a[mt][1] = __float_as_uint(hi.x);
                a[mt][2] = __float_as_uint(lo.y);
                a[mt][3] = __float_as_uint(hi.y);
            }
            unsigned b[8][2];
#pragma unroll
            for (int nt = 0; nt < 8; nt++) {
                int n = nbase + nt * 8 + g;
                float2 v = *(const float2*)(Bs + n * ROWSTR + kp);
                b[nt][0] = __float_as_uint(v.x);
                b[nt][1] = __float_as_uint(v.y);
            }
#pragma unroll
            for (int mt = 0; mt < 2; mt++)
#pragma unroll
                for (int nt = 0; nt < 8; nt++)
                    mma_tf32(acc[mt][nt], a[mt], b[nt]);
        }
    }

    // ---- epilogue ----
#pragma unroll
    for (int mt = 0; mt < 2; mt++) {
#pragma unroll
        for (int nt = 0; nt < 8; nt++) {
            int row = m0 + mbase + mt * 16 + g;
            int col = n0 + nbase + nt * 8 + 2 * t4;
            float2 v0 = make_float2(acc[mt][nt][0], acc[mt][nt][1]);
            float2 v1 = make_float2(acc[mt][nt][2], acc[mt][nt][3]);
            *(float2*)&g_U[(size_t)row * N_DIM + col] = v0;
            *(float2*)&g_U[(size_t)(row + 8) * N_DIM + col] = v1;
        }
    }
}

// ---------------------------------------------------------------------------
// Kernel 3: sequential SRU scan. One thread per (b,d) channel.
// ---------------------------------------------------------------------------
__global__ void __launch_bounds__(128) sru_scan(const float* __restrict__ X,
                                                const float* __restrict__ C0,
                                                const float* __restrict__ Wc,
                                                const float* __restrict__ Bias,
                                                float* __restrict__ Out,
                                                int write_c) {
    int ch = blockIdx.x * 128 + threadIdx.x;  // 0..16383
    int d = ch & (D_DIM - 1);

    float fw = Wc[d], rw = Wc[D_DIM + d];
    float fb = Bias[d], rb = Bias[D_DIM + d];
    float c = C0[ch];

    const float SC = 1.7320508075688772f;  // sqrt(1 + 2*e^0)
    const float* up = g_U + (size_t)(ch >> 10) * N_DIM + 3 * d;
    const float* xp = X + ch;
    float* hp = Out + ch;

#pragma unroll 4
    for (int l = 0; l < L_DIM; l++) {
        float u0 = up[0], u1 = up[1], u2 = up[2];
        float xv = xp[0] * SC;
        float z1 = fmaf(c, fw, u1 + fb);
        float z2 = fmaf(c, rw, u2 + rb);
        float f = 1.0f / (1.0f + __expf(-z1));
        float r = 1.0f / (1.0f + __expf(-z2));
        c = u0 + (c - u0) * f;
        hp[0] = xv + (c - xv) * r;
        up += B_DIM * N_DIM;
        xp += B_DIM * D_DIM;
        hp += B_DIM * D_DIM;
    }
    if (write_c) Out[(size_t)L_DIM * B_DIM * D_DIM + ch] = c;
}

// ---------------------------------------------------------------------------
extern "C" void kernel_launch(void* const* d_in, const int* in_sizes, int n_in,
                              void* d_out, int out_size) {
    const float* x    = (const float*)d_in[0];
    const float* c0   = (const float*)d_in[1];
    const float* w    = (const float*)d_in[2];
    const float* wc   = (const float*)d_in[3];
    const float* bias = (const float*)d_in[4];
    float* out = (float*)d_out;

    int write_c = (out_size >= L_DIM * B_DIM * D_DIM + B_DIM * D_DIM) ? 1 : 0;

    static int smem_set = 0;
    if (!smem_set) {
        cudaFuncSetAttribute(gemm_tf32, cudaFuncAttributeMaxDynamicSharedMemorySize,
                             GEMM_SMEM_BYTES);
        smem_set = 1;
    }

    round_x<<<(M_DIM * (K_DIM / 8)) / 256, 256>>>(x);   // 16384 blocks
    transpose_w<<<dim3(N_DIM / 32, K_DIM / 32), dim3(32, 8)>>>(w);
    gemm_tf32<<<dim3(N_DIM / BN, M_DIM / BM), 256, GEMM_SMEM_BYTES>>>();
    sru_scan<<<(B_DIM * D_DIM) / 128, 128>>>(x, c0, wc, bias, out, write_c);
}

// round 4
// speedup vs baseline: 1.3399x; 1.3399x over previous
#include <cuda_runtime.h>
#include <cuda_fp16.h>

// ============================================================================
// SRU cell. L=2048, B=16, D=1024.
//   u = x @ W  -> fp16 mma.sync m16n8k16 GEMM (fp16 mantissa == tf32 mantissa,
//                 fp32 accumulate; legacy tf32 path measured ~4x slower)
//   scan over L on 16384 channels -> scan kernel
// ============================================================================

#define L_DIM 2048
#define B_DIM 16
#define D_DIM 1024
#define N_DIM 3072
#define K_DIM 1024
#define M_DIM 32768  // L*B

#define BM 128
#define BN 128
#define BK 32                      // halves per stage
#define STAGES 4
#define ROWSTR_H 40                // halves per smem row (64B data + 16B pad)
#define KT (K_DIM / BK)            // 32
#define STAGE_H (2 * BM * ROWSTR_H)            // halves per stage (A+B) = 10240
#define GEMM_SMEM_BYTES (STAGES * STAGE_H * 2) // 81920

// Scratch (allocation-free rule: __device__ globals)
__device__ __half g_Xh[(size_t)M_DIM * K_DIM];  // X as fp16 (64 MB)
__device__ __half g_Wh[N_DIM * K_DIM];          // W^T as fp16 (6 MB)
__device__ float  g_U[(size_t)M_DIM * N_DIM];   // GEMM output u (402 MB)

// ---------------------------------------------------------------------------
__device__ __forceinline__ unsigned smem_u32(const void* p) {
    unsigned a;
    asm("{ .reg .u64 t; cvta.to.shared.u64 t, %1; cvt.u32.u64 %0, t; }" : "=r"(a) : "l"(p));
    return a;
}

__device__ __forceinline__ void cp_async16(unsigned dst, const void* src) {
    asm volatile("cp.async.cg.shared.global [%0], [%1], 16;" :: "r"(dst), "l"(src));
}

__device__ __forceinline__ void ldmatrix_x4(unsigned& r0, unsigned& r1,
                                            unsigned& r2, unsigned& r3, unsigned addr) {
    asm volatile("ldmatrix.sync.aligned.m8n8.x4.shared.b16 {%0,%1,%2,%3}, [%4];"
                 : "=r"(r0), "=r"(r1), "=r"(r2), "=r"(r3) : "r"(addr));
}

__device__ __forceinline__ void mma_f16(float* c, const unsigned* a, const unsigned* b) {
    asm volatile(
        "mma.sync.aligned.m16n8k16.row.col.f32.f16.f16.f32 "
        "{%0,%1,%2,%3}, {%4,%5,%6,%7}, {%8,%9}, {%0,%1,%2,%3};"
        : "+f"(c[0]), "+f"(c[1]), "+f"(c[2]), "+f"(c[3])
        : "r"(a[0]), "r"(a[1]), "r"(a[2]), "r"(a[3]), "r"(b[0]), "r"(b[1]));
}

// ---------------------------------------------------------------------------
// Kernel 0: convert X -> fp16 (8 elems/thread)
// ---------------------------------------------------------------------------
__global__ void __launch_bounds__(256) convert_x(const float* __restrict__ X) {
    size_t i = ((size_t)blockIdx.x * 256 + threadIdx.x) * 8;
    float4 a = *(const float4*)(X + i);
    float4 b = *(const float4*)(X + i + 4);
    __half2 h0 = __floats2half2_rn(a.x, a.y);
    __half2 h1 = __floats2half2_rn(a.z, a.w);
    __half2 h2 = __floats2half2_rn(b.x, b.y);
    __half2 h3 = __floats2half2_rn(b.z, b.w);
    uint4 o;
    o.x = *(unsigned*)&h0; o.y = *(unsigned*)&h1;
    o.z = *(unsigned*)&h2; o.w = *(unsigned*)&h3;
    *(uint4*)(g_Xh + i) = o;
}

// ---------------------------------------------------------------------------
// Kernel 1: transpose W (K,N) -> W^T (N,K) as fp16
// ---------------------------------------------------------------------------
__global__ void transpose_w(const float* __restrict__ W) {
    __shared__ float t[32][33];
    int n0 = blockIdx.x * 32, k0 = blockIdx.y * 32;
    int tx = threadIdx.x, ty = threadIdx.y;  // 32 x 8
#pragma unroll
    for (int i = 0; i < 32; i += 8)
        t[ty + i][tx] = W[(size_t)(k0 + ty + i) * N_DIM + n0 + tx];
    __syncthreads();
#pragma unroll
    for (int i = 0; i < 32; i += 8)
        g_Wh[(size_t)(n0 + ty + i) * K_DIM + k0 + tx] = __float2half_rn(t[tx][ty + i]);
}

// ---------------------------------------------------------------------------
// Kernel 2: fp16 GEMM. CTA 128x128, BK=32, 4-stage cp.async, ldmatrix + mma.
// 8 warps: 4(M) x 2(N); warp tile 32(M) x 64(N).
// ---------------------------------------------------------------------------
__global__ void __launch_bounds__(256, 2) gemm_f16() {
    extern __shared__ __half smem_h[];
    unsigned sbase = smem_u32(smem_h);

    int tid = threadIdx.x;
    int wid = tid >> 5;
    int lid = tid & 31;
    int g   = lid >> 2;
    int t4  = lid & 3;
    int q   = lid >> 3;     // lane quarter 0..3
    int rr  = lid & 7;      // row within ldmatrix
    int warp_m = wid >> 1;
    int warp_n = wid & 1;
    int mbase = warp_m * 32;
    int nbase = warp_n * 64;

    int n0 = blockIdx.x * BN;
    int m0 = blockIdx.y * BM;

    const __half* Arow = g_Xh + (size_t)m0 * K_DIM;
    const __half* Brow = g_Wh + (size_t)n0 * K_DIM;
    const int B_OFF_H = BM * ROWSTR_H;

    float acc[2][8][4];
#pragma unroll
    for (int mt = 0; mt < 2; mt++)
#pragma unroll
        for (int nt = 0; nt < 8; nt++)
#pragma unroll
            for (int i = 0; i < 4; i++) acc[mt][nt][i] = 0.0f;

    // stage: A 128 rows x 64B (4 chunks) + B same = 1024 chunks; 4/thread.
    auto load_stage = [&](int stage, int kc) {
        unsigned sA = sbase + (unsigned)(stage * STAGE_H) * 2u;
        unsigned sB = sA + (unsigned)B_OFF_H * 2u;
#pragma unroll
        for (int t = 0; t < 2; t++) {
            int j = tid + t * 256;          // 0..511
            int row = j >> 2;               // 0..127
            int c = j & 3;                  // 16B chunk within 64B row
            unsigned off = (unsigned)(row * ROWSTR_H + c * 8) * 2u;
            cp_async16(sA + off, Arow + (size_t)row * K_DIM + kc + c * 8);
            cp_async16(sB + off, Brow + (size_t)row * K_DIM + kc + c * 8);
        }
        asm volatile("cp.async.commit_group;" ::: "memory");
    };

#pragma unroll
    for (int s = 0; s < STAGES - 1; s++) load_stage(s, s * BK);

    for (int kt = 0; kt < KT; kt++) {
        asm volatile("cp.async.wait_group %0;" :: "n"(STAGES - 2) : "memory");
        __syncthreads();

        if (kt + STAGES - 1 < KT)
            load_stage((kt + STAGES - 1) % STAGES, (kt + STAGES - 1) * BK);
        else
            asm volatile("cp.async.commit_group;" ::: "memory");

        unsigned stA = sbase + (unsigned)((kt % STAGES) * STAGE_H) * 2u;
        unsigned stB = stA + (unsigned)B_OFF_H * 2u;

#pragma unroll
        for (int kk = 0; kk < 2; kk++) {
            // A frags: per mt one ldmatrix.x4 (16m x 16k)
            // matrices: {m-lo k-lo, m-hi k-lo, m-lo k-hi, m-hi k-hi}
            unsigned a[2][4];
#pragma unroll
            for (int mt = 0; mt < 2; mt++) {
                int row = mbase + mt * 16 + ((q & 1) << 3) + rr;
                int kh  = kk * 16 + (q >> 1) * 8;
                ldmatrix_x4(a[mt][0], a[mt][1], a[mt][2], a[mt][3],
                            stA + (unsigned)(row * ROWSTR_H + kh) * 2u);
            }
            // B frags: per nt-pair one ldmatrix.x4
            // matrices: {n-lo k-lo, n-lo k-hi, n-hi k-lo, n-hi k-hi}
            unsigned b[8][2];
#pragma unroll
            for (int nt2 = 0; nt2 < 4; nt2++) {
                int row = nbase + nt2 * 16 + ((q >> 1) << 3) + rr;
                int kh  = kk * 16 + (q & 1) * 8;
                ldmatrix_x4(b[nt2 * 2][0], b[nt2 * 2][1], b[nt2 * 2 + 1][0], b[nt2 * 2 + 1][1],
                            stB + (unsigned)(row * ROWSTR_H + kh) * 2u);
            }
#pragma unroll
            for (int mt = 0; mt < 2; mt++)
#pragma unroll
                for (int nt = 0; nt < 8; nt++)
                    mma_f16(acc[mt][nt], a[mt], b[nt]);
        }
    }

    // ---- epilogue (c layout of m16n8k16 == m16n8k8) ----
#pragma unroll
    for (int mt = 0; mt < 2; mt++) {
#pragma unroll
        for (int nt = 0; nt < 8; nt++) {
            int row = m0 + mbase + mt * 16 + g;
            int col = n0 + nbase + nt * 8 + 2 * t4;
            float2 v0 = make_float2(acc[mt][nt][0], acc[mt][nt][1]);
            float2 v1 = make_float2(acc[mt][nt][2], acc[mt][nt][3]);
            *(float2*)&g_U[(size_t)row * N_DIM + col] = v0;
            *(float2*)&g_U[(size_t)(row + 8) * N_DIM + col] = v1;
        }
    }
}

// ---------------------------------------------------------------------------
// Kernel 3: sequential SRU scan. One thread per (b,d) channel.
// ---------------------------------------------------------------------------
__global__ void __launch_bounds__(128) sru_scan(const float* __restrict__ X,
                                                const float* __restrict__ C0,
                                                const float* __restrict__ Wc,
                                                const float* __restrict__ Bias,
                                                float* __restrict__ Out,
                                                int write_c) {
    int ch = blockIdx.x * 128 + threadIdx.x;  // 0..16383
    int d = ch & (D_DIM - 1);

    float fw = Wc[d], rw = Wc[D_DIM + d];
    float fb = Bias[d], rb = Bias[D_DIM + d];
    float c = C0[ch];

    const float SC = 1.7320508075688772f;  // sqrt(1 + 2*e^0)
    const float* up = g_U + (size_t)(ch >> 10) * N_DIM + 3 * d;
    const float* xp = X + ch;
    float* hp = Out + ch;

#pragma unroll 4
    for (int l = 0; l < L_DIM; l++) {
        float u0 = up[0], u1 = up[1], u2 = up[2];
        float xv = xp[0] * SC;
        float z1 = fmaf(c, fw, u1 + fb);
        float z2 = fmaf(c, rw, u2 + rb);
        float f = 1.0f / (1.0f + __expf(-z1));
        float r = 1.0f / (1.0f + __expf(-z2));
        c = u0 + (c - u0) * f;
        hp[0] = xv + (c - xv) * r;
        up += B_DIM * N_DIM;
        xp += B_DIM * D_DIM;
        hp += B_DIM * D_DIM;
    }
    if (write_c) Out[(size_t)L_DIM * B_DIM * D_DIM + ch] = c;
}

// ---------------------------------------------------------------------------
extern "C" void kernel_launch(void* const* d_in, const int* in_sizes, int n_in,
                              void* d_out, int out_size) {
    const float* x    = (const float*)d_in[0];
    const float* c0   = (const float*)d_in[1];
    const float* w    = (const float*)d_in[2];
    const float* wc   = (const float*)d_in[3];
    const float* bias = (const float*)d_in[4];
    float* out = (float*)d_out;

    int write_c = (out_size >= L_DIM * B_DIM * D_DIM + B_DIM * D_DIM) ? 1 : 0;

    static int smem_set = 0;
    if (!smem_set) {
        cudaFuncSetAttribute(gemm_f16, cudaFuncAttributeMaxDynamicSharedMemorySize,
                             GEMM_SMEM_BYTES);
        smem_set = 1;
    }

    convert_x<<<(M_DIM * (K_DIM / 8)) / 256, 256>>>(x);
    transpose_w<<<dim3(N_DIM / 32, K_DIM / 32), dim3(32, 8)>>>(w);
    gemm_f16<<<dim3(N_DIM / BN, M_DIM / BM), 256, GEMM_SMEM_BYTES>>>();
    sru_scan<<<(B_DIM * D_DIM) / 128, 128>>>(x, c0, wc, bias, out, write_c);
}

// round 5
// speedup vs baseline: 1.8329x; 1.3680x over previous
#include <cuda_runtime.h>
#include <cuda_fp16.h>

// ============================================================================
// SRU cell. L=2048, B=16, D=1024.
//   u = x @ W  -> fp16 mma.sync m16n8k16, fp16 accumulate (2x legacy-pipe rate
//                 hypothesis) promoted per-mma into fp32 registers.
//   U stored as fp16 (halves HBM traffic GEMM->scan).
//   scan over L on 16384 channels, software-pipelined prefetch.
// ============================================================================

#define L_DIM 2048
#define B_DIM 16
#define D_DIM 1024
#define N_DIM 3072
#define K_DIM 1024
#define M_DIM 32768  // L*B

#define BM 128
#define BN 128
#define BK 32
#define STAGES 4
#define ROWSTR_H 40                // halves per smem row (64B data + 16B pad)
#define KT (K_DIM / BK)            // 32
#define STAGE_H (2 * BM * ROWSTR_H)            // 10240 halves
#define GEMM_SMEM_BYTES (STAGES * STAGE_H * 2) // 81920

// Scratch (allocation-free rule: __device__ globals)
__device__ __half g_Xh[(size_t)M_DIM * K_DIM];  // X fp16 (64 MB)
__device__ __half g_Wh[N_DIM * K_DIM];          // W^T fp16 (6 MB)
__device__ __half g_Uh[(size_t)M_DIM * N_DIM];  // GEMM output u, fp16 (201 MB)

// ---------------------------------------------------------------------------
__device__ __forceinline__ unsigned smem_u32(const void* p) {
    unsigned a;
    asm("{ .reg .u64 t; cvta.to.shared.u64 t, %1; cvt.u32.u64 %0, t; }" : "=r"(a) : "l"(p));
    return a;
}

__device__ __forceinline__ void cp_async16(unsigned dst, const void* src) {
    asm volatile("cp.async.cg.shared.global [%0], [%1], 16;" :: "r"(dst), "l"(src));
}

__device__ __forceinline__ void ldmatrix_x4(unsigned& r0, unsigned& r1,
                                            unsigned& r2, unsigned& r3, unsigned addr) {
    asm volatile("ldmatrix.sync.aligned.m8n8.x4.shared.b16 {%0,%1,%2,%3}, [%4];"
                 : "=r"(r0), "=r"(r1), "=r"(r2), "=r"(r3) : "r"(addr));
}

// fp16-accumulate mma, c-in = 0, returns packed half2 pair
__device__ __forceinline__ void mma_f16acc(unsigned& c0, unsigned& c1,
                                           const unsigned* a, const unsigned* b) {
    c0 = 0u; c1 = 0u;
    asm volatile(
        "mma.sync.aligned.m16n8k16.row.col.f16.f16.f16.f16 "
        "{%0,%1}, {%2,%3,%4,%5}, {%6,%7}, {%0,%1};"
        : "+r"(c0), "+r"(c1)
        : "r"(a[0]), "r"(a[1]), "r"(a[2]), "r"(a[3]), "r"(b[0]), "r"(b[1]));
}

// ---------------------------------------------------------------------------
// Kernel 0: convert X -> fp16
// ---------------------------------------------------------------------------
__global__ void __launch_bounds__(256) convert_x(const float* __restrict__ X) {
    size_t i = ((size_t)blockIdx.x * 256 + threadIdx.x) * 8;
    float4 a = *(const float4*)(X + i);
    float4 b = *(const float4*)(X + i + 4);
    __half2 h0 = __floats2half2_rn(a.x, a.y);
    __half2 h1 = __floats2half2_rn(a.z, a.w);
    __half2 h2 = __floats2half2_rn(b.x, b.y);
    __half2 h3 = __floats2half2_rn(b.z, b.w);
    uint4 o;
    o.x = *(unsigned*)&h0; o.y = *(unsigned*)&h1;
    o.z = *(unsigned*)&h2; o.w = *(unsigned*)&h3;
    *(uint4*)(g_Xh + i) = o;
}

// ---------------------------------------------------------------------------
// Kernel 1: transpose W (K,N) -> W^T (N,K) fp16
// ---------------------------------------------------------------------------
__global__ void transpose_w(const float* __restrict__ W) {
    __shared__ float t[32][33];
    int n0 = blockIdx.x * 32, k0 = blockIdx.y * 32;
    int tx = threadIdx.x, ty = threadIdx.y;  // 32 x 8
#pragma unroll
    for (int i = 0; i < 32; i += 8)
        t[ty + i][tx] = W[(size_t)(k0 + ty + i) * N_DIM + n0 + tx];
    __syncthreads();
#pragma unroll
    for (int i = 0; i < 32; i += 8)
        g_Wh[(size_t)(n0 + ty + i) * K_DIM + k0 + tx] = __float2half_rn(t[tx][ty + i]);
}

// ---------------------------------------------------------------------------
// Kernel 2: fp16 GEMM, fp16-acc mma + per-mma fp32 promotion.
// CTA 128x128, BK=32, 4-stage cp.async, 8 warps 4(M)x2(N), warp 32x64.
// ---------------------------------------------------------------------------
__global__ void __launch_bounds__(256, 2) gemm_f16() {
    extern __shared__ __half smem_h[];
    unsigned sbase = smem_u32(smem_h);

    int tid = threadIdx.x;
    int wid = tid >> 5;
    int lid = tid & 31;
    int g   = lid >> 2;
    int t4  = lid & 3;
    int q   = lid >> 3;
    int rr  = lid & 7;
    int warp_m = wid >> 1;
    int warp_n = wid & 1;
    int mbase = warp_m * 32;
    int nbase = warp_n * 64;

    int n0 = blockIdx.x * BN;
    int m0 = blockIdx.y * BM;

    const __half* Arow = g_Xh + (size_t)m0 * K_DIM;
    const __half* Brow = g_Wh + (size_t)n0 * K_DIM;
    const int B_OFF_H = BM * ROWSTR_H;

    float acc[2][8][4];
#pragma unroll
    for (int mt = 0; mt < 2; mt++)
#pragma unroll
        for (int nt = 0; nt < 8; nt++)
#pragma unroll
            for (int i = 0; i < 4; i++) acc[mt][nt][i] = 0.0f;

    auto load_stage = [&](int stage, int kc) {
        unsigned sA = sbase + (unsigned)(stage * STAGE_H) * 2u;
        unsigned sB = sA + (unsigned)B_OFF_H * 2u;
#pragma unroll
        for (int t = 0; t < 2; t++) {
            int j = tid + t * 256;
            int row = j >> 2;
            int c = j & 3;
            unsigned off = (unsigned)(row * ROWSTR_H + c * 8) * 2u;
            cp_async16(sA + off, Arow + (size_t)row * K_DIM + kc + c * 8);
            cp_async16(sB + off, Brow + (size_t)row * K_DIM + kc + c * 8);
        }
        asm volatile("cp.async.commit_group;" ::: "memory");
    };

#pragma unroll
    for (int s = 0; s < STAGES - 1; s++) load_stage(s, s * BK);

    for (int kt = 0; kt < KT; kt++) {
        asm volatile("cp.async.wait_group %0;" :: "n"(STAGES - 2) : "memory");
        __syncthreads();

        if (kt + STAGES - 1 < KT)
            load_stage((kt + STAGES - 1) % STAGES, (kt + STAGES - 1) * BK);
        else
            asm volatile("cp.async.commit_group;" ::: "memory");

        unsigned stA = sbase + (unsigned)((kt % STAGES) * STAGE_H) * 2u;
        unsigned stB = stA + (unsigned)B_OFF_H * 2u;

#pragma unroll
        for (int kk = 0; kk < 2; kk++) {
            unsigned a[2][4];
#pragma unroll
            for (int mt = 0; mt < 2; mt++) {
                int row = mbase + mt * 16 + ((q & 1) << 3) + rr;
                int kh  = kk * 16 + (q >> 1) * 8;
                ldmatrix_x4(a[mt][0], a[mt][1], a[mt][2], a[mt][3],
                            stA + (unsigned)(row * ROWSTR_H + kh) * 2u);
            }
            unsigned b[8][2];
#pragma unroll
            for (int nt2 = 0; nt2 < 4; nt2++) {
                int row = nbase + nt2 * 16 + ((q >> 1) << 3) + rr;
                int kh  = kk * 16 + (q & 1) * 8;
                ldmatrix_x4(b[nt2 * 2][0], b[nt2 * 2][1], b[nt2 * 2 + 1][0], b[nt2 * 2 + 1][1],
                            stB + (unsigned)(row * ROWSTR_H + kh) * 2u);
            }
#pragma unroll
            for (int mt = 0; mt < 2; mt++)
#pragma unroll
                for (int nt = 0; nt < 8; nt++) {
                    unsigned c0, c1;
                    mma_f16acc(c0, c1, a[mt], b[nt]);
                    float2 f0 = __half22float2(*(__half2*)&c0);
                    float2 f1 = __half22float2(*(__half2*)&c1);
                    acc[mt][nt][0] += f0.x;
                    acc[mt][nt][1] += f0.y;
                    acc[mt][nt][2] += f1.x;
                    acc[mt][nt][3] += f1.y;
                }
        }
    }

    // ---- epilogue: fp32 acc -> fp16 U ----
#pragma unroll
    for (int mt = 0; mt < 2; mt++) {
#pragma unroll
        for (int nt = 0; nt < 8; nt++) {
            int row = m0 + mbase + mt * 16 + g;
            int col = n0 + nbase + nt * 8 + 2 * t4;
            __half2 o0 = __floats2half2_rn(acc[mt][nt][0], acc[mt][nt][1]);
            __half2 o1 = __floats2half2_rn(acc[mt][nt][2], acc[mt][nt][3]);
            *(unsigned*)&g_Uh[(size_t)row * N_DIM + col] = *(unsigned*)&o0;
            *(unsigned*)&g_Uh[(size_t)(row + 8) * N_DIM + col] = *(unsigned*)&o1;
        }
    }
}

// ---------------------------------------------------------------------------
// Kernel 3: SRU scan, software-pipelined (prefetch next 4 steps).
// ---------------------------------------------------------------------------
__global__ void __launch_bounds__(128) sru_scan(const float* __restrict__ X,
                                                const float* __restrict__ C0,
                                                const float* __restrict__ Wc,
                                                const float* __restrict__ Bias,
                                                float* __restrict__ Out,
                                                int write_c) {
    int ch = blockIdx.x * 128 + threadIdx.x;  // 0..16383
    int d = ch & (D_DIM - 1);

    float fw = Wc[d], rw = Wc[D_DIM + d];
    float fb = Bias[d], rb = Bias[D_DIM + d];
    float c = C0[ch];

    const float SC = 1.7320508075688772f;
    const __half* up = g_Uh + (size_t)(ch >> 10) * N_DIM + 3 * d;
    const float* xp = X + ch;
    float* hp = Out + ch;

    const int US = B_DIM * N_DIM;   // u stride per step (halves)
    const int XS = B_DIM * D_DIM;   // x stride per step

    float pu0[4], pu1[4], pu2[4], px[4];
#pragma unroll
    for (int j = 0; j < 4; j++) {
        const __half* u = up + (size_t)j * US;
        pu0[j] = __half2float(u[0]);
        pu1[j] = __half2float(u[1]);
        pu2[j] = __half2float(u[2]);
        px[j]  = xp[(size_t)j * XS];
    }

    for (int l = 0; l < L_DIM; l += 4) {
        float cu0[4], cu1[4], cu2[4], cx[4];
#pragma unroll
        for (int j = 0; j < 4; j++) {
            cu0[j] = pu0[j]; cu1[j] = pu1[j]; cu2[j] = pu2[j]; cx[j] = px[j];
        }
        if (l + 4 < L_DIM) {
#pragma unroll
            for (int j = 0; j < 4; j++) {
                const __half* u = up + (size_t)(j + 4) * US;
                pu0[j] = __half2float(u[0]);
                pu1[j] = __half2float(u[1]);
                pu2[j] = __half2float(u[2]);
                px[j]  = xp[(size_t)(j + 4) * XS];
            }
        }
#pragma unroll
        for (int j = 0; j < 4; j++) {
            float xv = cx[j] * SC;
            float z1 = fmaf(c, fw, cu1[j] + fb);
            float z2 = fmaf(c, rw, cu2[j] + rb);
            float f = 1.0f / (1.0f + __expf(-z1));
            float r = 1.0f / (1.0f + __expf(-z2));
            c = cu0[j] + (c - cu0[j]) * f;
            hp[(size_t)j * XS] = xv + (c - xv) * r;
        }
        up += (size_t)4 * US;
        xp += (size_t)4 * XS;
        hp += (size_t)4 * XS;
    }
    if (write_c) Out[(size_t)L_DIM * B_DIM * D_DIM + ch] = c;
}

// ---------------------------------------------------------------------------
extern "C" void kernel_launch(void* const* d_in, const int* in_sizes, int n_in,
                              void* d_out, int out_size) {
    const float* x    = (const float*)d_in[0];
    const float* c0   = (const float*)d_in[1];
    const float* w    = (const float*)d_in[2];
    const float* wc   = (const float*)d_in[3];
    const float* bias = (const float*)d_in[4];
    float* out = (float*)d_out;

    int write_c = (out_size >= L_DIM * B_DIM * D_DIM + B_DIM * D_DIM) ? 1 : 0;

    static int smem_set = 0;
    if (!smem_set) {
        cudaFuncSetAttribute(gemm_f16, cudaFuncAttributeMaxDynamicSharedMemorySize,
                             GEMM_SMEM_BYTES);
        smem_set = 1;
    }

    convert_x<<<(M_DIM * (K_DIM / 8)) / 256, 256>>>(x);
    transpose_w<<<dim3(N_DIM / 32, K_DIM / 32), dim3(32, 8)>>>(w);
    gemm_f16<<<dim3(N_DIM / BN, M_DIM / BM), 256, GEMM_SMEM_BYTES>>>();
    sru_scan<<<(B_DIM * D_DIM) / 128, 128>>>(x, c0, wc, bias, out, write_c);
}

// round 6
// speedup vs baseline: 2.1396x; 1.1673x over previous
#include <cuda_runtime.h>
#include <cuda_fp16.h>

// ============================================================================
// SRU cell. L=2048, B=16, D=1024.
//   u = x @ W  -> fp16 mma.sync m16n8k16, fp16 accumulate promoted per-mma
//                 into fp32 registers (legacy-pipe rate-bound, ~measured).
//   U stored as fp16.
//   scan over L on 16384 channels: deep (16-step) double-buffered prefetch.
// ============================================================================

#define L_DIM 2048
#define B_DIM 16
#define D_DIM 1024
#define N_DIM 3072
#define K_DIM 1024
#define M_DIM 32768  // L*B

#define BM 128
#define BN 128
#define BK 32
#define STAGES 4
#define ROWSTR_H 40                // halves per smem row (64B data + 16B pad)
#define KT (K_DIM / BK)            // 32
#define STAGE_H (2 * BM * ROWSTR_H)            // 10240 halves
#define GEMM_SMEM_BYTES (STAGES * STAGE_H * 2) // 81920

// Scratch (allocation-free rule: __device__ globals)
__device__ __half g_Xh[(size_t)M_DIM * K_DIM];  // X fp16 (64 MB)
__device__ __half g_Wh[N_DIM * K_DIM];          // W^T fp16 (6 MB)
__device__ __half g_Uh[(size_t)M_DIM * N_DIM];  // GEMM output u, fp16 (201 MB)

// ---------------------------------------------------------------------------
__device__ __forceinline__ unsigned smem_u32(const void* p) {
    unsigned a;
    asm("{ .reg .u64 t; cvta.to.shared.u64 t, %1; cvt.u32.u64 %0, t; }" : "=r"(a) : "l"(p));
    return a;
}

__device__ __forceinline__ void cp_async16(unsigned dst, const void* src) {
    asm volatile("cp.async.cg.shared.global [%0], [%1], 16;" :: "r"(dst), "l"(src));
}

__device__ __forceinline__ void ldmatrix_x4(unsigned& r0, unsigned& r1,
                                            unsigned& r2, unsigned& r3, unsigned addr) {
    asm volatile("ldmatrix.sync.aligned.m8n8.x4.shared.b16 {%0,%1,%2,%3}, [%4];"
                 : "=r"(r0), "=r"(r1), "=r"(r2), "=r"(r3) : "r"(addr));
}

// fp16-accumulate mma, c-in = 0
__device__ __forceinline__ void mma_f16acc(unsigned& c0, unsigned& c1,
                                           const unsigned* a, const unsigned* b) {
    c0 = 0u; c1 = 0u;
    asm volatile(
        "mma.sync.aligned.m16n8k16.row.col.f16.f16.f16.f16 "
        "{%0,%1}, {%2,%3,%4,%5}, {%6,%7}, {%0,%1};"
        : "+r"(c0), "+r"(c1)
        : "r"(a[0]), "r"(a[1]), "r"(a[2]), "r"(a[3]), "r"(b[0]), "r"(b[1]));
}

// ---------------------------------------------------------------------------
// Kernel 0: convert X -> fp16
// ---------------------------------------------------------------------------
__global__ void __launch_bounds__(256) convert_x(const float* __restrict__ X) {
    size_t i = ((size_t)blockIdx.x * 256 + threadIdx.x) * 8;
    float4 a = *(const float4*)(X + i);
    float4 b = *(const float4*)(X + i + 4);
    __half2 h0 = __floats2half2_rn(a.x, a.y);
    __half2 h1 = __floats2half2_rn(a.z, a.w);
    __half2 h2 = __floats2half2_rn(b.x, b.y);
    __half2 h3 = __floats2half2_rn(b.z, b.w);
    uint4 o;
    o.x = *(unsigned*)&h0; o.y = *(unsigned*)&h1;
    o.z = *(unsigned*)&h2; o.w = *(unsigned*)&h3;
    *(uint4*)(g_Xh + i) = o;
}

// ---------------------------------------------------------------------------
// Kernel 1: transpose W (K,N) -> W^T (N,K) fp16
// ---------------------------------------------------------------------------
__global__ void transpose_w(const float* __restrict__ W) {
    __shared__ float t[32][33];
    int n0 = blockIdx.x * 32, k0 = blockIdx.y * 32;
    int tx = threadIdx.x, ty = threadIdx.y;  // 32 x 8
#pragma unroll
    for (int i = 0; i < 32; i += 8)
        t[ty + i][tx] = W[(size_t)(k0 + ty + i) * N_DIM + n0 + tx];
    __syncthreads();
#pragma unroll
    for (int i = 0; i < 32; i += 8)
        g_Wh[(size_t)(n0 + ty + i) * K_DIM + k0 + tx] = __float2half_rn(t[tx][ty + i]);
}

// ---------------------------------------------------------------------------
// Kernel 2: fp16 GEMM, fp16-acc mma + per-mma fp32 promotion.
// CTA 128x128, BK=32, 4-stage cp.async, 8 warps 4(M)x2(N), warp 32x64.
// ---------------------------------------------------------------------------
__global__ void __launch_bounds__(256, 2) gemm_f16() {
    extern __shared__ __half smem_h[];
    unsigned sbase = smem_u32(smem_h);

    int tid = threadIdx.x;
    int wid = tid >> 5;
    int lid = tid & 31;
    int g   = lid >> 2;
    int t4  = lid & 3;
    int q   = lid >> 3;
    int rr  = lid & 7;
    int warp_m = wid >> 1;
    int warp_n = wid & 1;
    int mbase = warp_m * 32;
    int nbase = warp_n * 64;

    int n0 = blockIdx.x * BN;
    int m0 = blockIdx.y * BM;

    const __half* Arow = g_Xh + (size_t)m0 * K_DIM;
    const __half* Brow = g_Wh + (size_t)n0 * K_DIM;
    const int B_OFF_H = BM * ROWSTR_H;

    float acc[2][8][4];
#pragma unroll
    for (int mt = 0; mt < 2; mt++)
#pragma unroll
        for (int nt = 0; nt < 8; nt++)
#pragma unroll
            for (int i = 0; i < 4; i++) acc[mt][nt][i] = 0.0f;

    auto load_stage = [&](int stage, int kc) {
        unsigned sA = sbase + (unsigned)(stage * STAGE_H) * 2u;
        unsigned sB = sA + (unsigned)B_OFF_H * 2u;
#pragma unroll
        for (int t = 0; t < 2; t++) {
            int j = tid + t * 256;
            int row = j >> 2;
            int c = j & 3;
            unsigned off = (unsigned)(row * ROWSTR_H + c * 8) * 2u;
            cp_async16(sA + off, Arow + (size_t)row * K_DIM + kc + c * 8);
            cp_async16(sB + off, Brow + (size_t)row * K_DIM + kc + c * 8);
        }
        asm volatile("cp.async.commit_group;" ::: "memory");
    };

#pragma unroll
    for (int s = 0; s < STAGES - 1; s++) load_stage(s, s * BK);

    for (int kt = 0; kt < KT; kt++) {
        asm volatile("cp.async.wait_group %0;" :: "n"(STAGES - 2) : "memory");
        __syncthreads();

        if (kt + STAGES - 1 < KT)
            load_stage((kt + STAGES - 1) % STAGES, (kt + STAGES - 1) * BK);
        else
            asm volatile("cp.async.commit_group;" ::: "memory");

        unsigned stA = sbase + (unsigned)((kt % STAGES) * STAGE_H) * 2u;
        unsigned stB = stA + (unsigned)B_OFF_H * 2u;

#pragma unroll
        for (int kk = 0; kk < 2; kk++) {
            unsigned a[2][4];
#pragma unroll
            for (int mt = 0; mt < 2; mt++) {
                int row = mbase + mt * 16 + ((q & 1) << 3) + rr;
                int kh  = kk * 16 + (q >> 1) * 8;
                ldmatrix_x4(a[mt][0], a[mt][1], a[mt][2], a[mt][3],
                            stA + (unsigned)(row * ROWSTR_H + kh) * 2u);
            }
            unsigned b[8][2];
#pragma unroll
            for (int nt2 = 0; nt2 < 4; nt2++) {
                int row = nbase + nt2 * 16 + ((q >> 1) << 3) + rr;
                int kh  = kk * 16 + (q & 1) * 8;
                ldmatrix_x4(b[nt2 * 2][0], b[nt2 * 2][1], b[nt2 * 2 + 1][0], b[nt2 * 2 + 1][1],
                            stB + (unsigned)(row * ROWSTR_H + kh) * 2u);
            }
#pragma unroll
            for (int mt = 0; mt < 2; mt++)
#pragma unroll
                for (int nt = 0; nt < 8; nt++) {
                    unsigned c0, c1;
                    mma_f16acc(c0, c1, a[mt], b[nt]);
                    float2 f0 = __half22float2(*(__half2*)&c0);
                    float2 f1 = __half22float2(*(__half2*)&c1);
                    acc[mt][nt][0] += f0.x;
                    acc[mt][nt][1] += f0.y;
                    acc[mt][nt][2] += f1.x;
                    acc[mt][nt][3] += f1.y;
                }
        }
    }

    // ---- epilogue: fp32 acc -> fp16 U ----
#pragma unroll
    for (int mt = 0; mt < 2; mt++) {
#pragma unroll
        for (int nt = 0; nt < 8; nt++) {
            int row = m0 + mbase + mt * 16 + g;
            int col = n0 + nbase + nt * 8 + 2 * t4;
            __half2 o0 = __floats2half2_rn(acc[mt][nt][0], acc[mt][nt][1]);
            __half2 o1 = __floats2half2_rn(acc[mt][nt][2], acc[mt][nt][3]);
            *(unsigned*)&g_Uh[(size_t)row * N_DIM + col] = *(unsigned*)&o0;
            *(unsigned*)&g_Uh[(size_t)(row + 8) * N_DIM + col] = *(unsigned*)&o1;
        }
    }
}

// ---------------------------------------------------------------------------
// Kernel 3: SRU scan, 16-step double-buffered register prefetch.
// One thread per (b,d) channel; 64-thread blocks so all 148 SMs are active.
// ---------------------------------------------------------------------------
#define PF 16

__global__ void __launch_bounds__(64) sru_scan(const float* __restrict__ X,
                                               const float* __restrict__ C0,
                                               const float* __restrict__ Wc,
                                               const float* __restrict__ Bias,
                                               float* __restrict__ Out,
                                               int write_c) {
    int ch = blockIdx.x * 64 + threadIdx.x;  // 0..16383
    int d = ch & (D_DIM - 1);

    float fw = Wc[d], rw = Wc[D_DIM + d];
    float fb = Bias[d], rb = Bias[D_DIM + d];
    float c = C0[ch];

    const float SC = 1.7320508075688772f;  // sqrt(1 + 2*e^0)
    const __half* up = g_Uh + (size_t)(ch >> 10) * N_DIM + 3 * d;
    const float* xp = X + ch;
    float* hp = Out + ch;

    const int US = B_DIM * N_DIM;   // u stride per step (halves)
    const int XS = B_DIM * D_DIM;   // x stride per step (floats)

    float bu0[2][PF], bu1[2][PF], bu2[2][PF], bx[2][PF];

    // preload group 0
#pragma unroll
    for (int j = 0; j < PF; j++) {
        const __half* u = up + (size_t)j * US;
        bu0[0][j] = __half2float(u[0]);
        bu1[0][j] = __half2float(u[1]);
        bu2[0][j] = __half2float(u[2]);
        bx[0][j]  = xp[(size_t)j * XS];
    }

#pragma unroll 2
    for (int l = 0; l < L_DIM; l += PF) {
        int p = (l / PF) & 1;
        // prefetch next group into the other buffer (no dependence on compute)
        if (l + PF < L_DIM) {
#pragma unroll
            for (int j = 0; j < PF; j++) {
                const __half* u = up + (size_t)(PF + j) * US;
                bu0[p ^ 1][j] = __half2float(u[0]);
                bu1[p ^ 1][j] = __half2float(u[1]);
                bu2[p ^ 1][j] = __half2float(u[2]);
                bx[p ^ 1][j]  = xp[(size_t)(PF + j) * XS];
            }
        }
        // compute current group
#pragma unroll
        for (int j = 0; j < PF; j++) {
            float xv = bx[p][j] * SC;
            float z1 = fmaf(c, fw, bu1[p][j] + fb);
            float z2 = fmaf(c, rw, bu2[p][j] + rb);
            float f = 1.0f / (1.0f + __expf(-z1));
            float r = 1.0f / (1.0f + __expf(-z2));
            c = bu0[p][j] + (c - bu0[p][j]) * f;
            hp[(size_t)j * XS] = xv + (c - xv) * r;
        }
        up += (size_t)PF * US;
        xp += (size_t)PF * XS;
        hp += (size_t)PF * XS;
    }
    if (write_c) Out[(size_t)L_DIM * B_DIM * D_DIM + ch] = c;
}

// ---------------------------------------------------------------------------
extern "C" void kernel_launch(void* const* d_in, const int* in_sizes, int n_in,
                              void* d_out, int out_size) {
    const float* x    = (const float*)d_in[0];
    const float* c0   = (const float*)d_in[1];
    const float* w    = (const float*)d_in[2];
    const float* wc   = (const float*)d_in[3];
    const float* bias = (const float*)d_in[4];
    float* out = (float*)d_out;

    int write_c = (out_size >= L_DIM * B_DIM * D_DIM + B_DIM * D_DIM) ? 1 : 0;

    static int smem_set = 0;
    if (!smem_set) {
        cudaFuncSetAttribute(gemm_f16, cudaFuncAttributeMaxDynamicSharedMemorySize,
                             GEMM_SMEM_BYTES);
        smem_set = 1;
    }

    convert_x<<<(M_DIM * (K_DIM / 8)) / 256, 256>>>(x);
    transpose_w<<<dim3(N_DIM / 32, K_DIM / 32), dim3(32, 8)>>>(w);
    gemm_f16<<<dim3(N_DIM / BN, M_DIM / BM), 256, GEMM_SMEM_BYTES>>>();
    sru_scan<<<(B_DIM * D_DIM) / 64, 64>>>(x, c0, wc, bias, out, write_c);
}